// round 16
// baseline (speedup 1.0000x reference)
#include <cuda_runtime.h>
#include <cstdint>

#define BATCH 4
#define NDIM 4096
#define CDIM 64
#define RDIM 16
#define TS 32           // k_sym tile
#define NT (NDIM / TS)  // 128 tiles per dim

// ---------------- scratch (device globals; no allocations) ----------------
__device__ float g_K0[(size_t)BATCH * NDIM * NDIM];   // 268 MB: Ws * A
__device__ float g_part[BATCH * NT * NDIM];           // 8 MB: deg partials
__device__ float g_d[BATCH * NDIM];                   // rsqrt(deg)

// ---------------- helpers ----------------
__device__ __forceinline__ float fast_sigmoid(float z) {
    float az = fabsf(z);
    if (az < 0.25f) {
        // sigmoid Taylor: 1/2 + z/4 - z^3/48 + z^5/480 ; err <= |z|^7*17/80640
        float z2 = z * z;
        return 0.5f + z * (0.25f + z2 * (-1.0f / 48.0f + z2 * (1.0f / 480.0f)));
    }
    return 1.0f / (1.0f + __expf(-z));
}

__device__ __forceinline__ unsigned long long pack2(float lo, float hi) {
    unsigned long long r;
    asm("mov.b64 %0, {%1, %2};" : "=l"(r) : "f"(lo), "f"(hi));
    return r;
}
__device__ __forceinline__ float2 unpack2(unsigned long long v) {
    float2 f;
    asm("mov.b64 {%0, %1}, %2;" : "=f"(f.x), "=f"(f.y) : "l"(v));
    return f;
}
__device__ __forceinline__ void fma2(unsigned long long& d,
                                     unsigned long long a,
                                     unsigned long long b) {
    asm("fma.rn.f32x2 %0, %1, %2, %3;" : "=l"(d) : "l"(a), "l"(b), "l"(d));
}

// ---------------- kernel 1: symmetric K0 = Ws .* A, deg partials ----------
// grid (NT, NT): blockIdx.x = jt, blockIdx.y = it, process only jt >= it.
// 256 threads: ty = tid>>3 (row 0..31), tx = tid&7 (4-col group).
__global__ void __launch_bounds__(256) k_sym(const float* __restrict__ W,
                                             const float* __restrict__ U) {
    const int jt = blockIdx.x;
    const int it = blockIdx.y;
    if (jt < it) return;

    __shared__ float A_s[TS][TS + 1];
    __shared__ float T1[TS][TS + 1];
    __shared__ float T2[TS][TS + 1];
    __shared__ float Ui[TS][RDIM + 1];
    __shared__ float Uj[TS][RDIM + 1];

    const int tid = threadIdx.x;
    const int tx = tid & 7;
    const int ty = tid >> 3;
    const int i0 = it * TS;
    const int j0 = jt * TS;

    // load U tiles (32 rows x 16) : threads 0..127 -> Ui, 128..255 -> Uj
    {
        int t = tid & 127;
        int r = t >> 2;
        int q = t & 3;
        if (tid < 128) {
            float4 v = *(const float4*)&U[(size_t)(i0 + r) * RDIM + q * 4];
            Ui[r][q * 4 + 0] = v.x; Ui[r][q * 4 + 1] = v.y;
            Ui[r][q * 4 + 2] = v.z; Ui[r][q * 4 + 3] = v.w;
        } else {
            float4 v = *(const float4*)&U[(size_t)(j0 + r) * RDIM + q * 4];
            Uj[r][q * 4 + 0] = v.x; Uj[r][q * 4 + 1] = v.y;
            Uj[r][q * 4 + 2] = v.z; Uj[r][q * 4 + 3] = v.w;
        }
    }
    __syncthreads();

    // A tile: thread handles row ty, cols 4*tx .. 4*tx+3
    {
        float ui[RDIM];
#pragma unroll
        for (int k = 0; k < RDIM; k++) ui[k] = Ui[ty][k];
#pragma unroll
        for (int jj = 0; jj < 4; jj++) {
            int j = 4 * tx + jj;
            float z = 0.0f;
#pragma unroll
            for (int k = 0; k < RDIM; k++) z = fmaf(ui[k], Uj[j][k], z);
            A_s[ty][j] = fast_sigmoid(z);
        }
    }
    __syncthreads();

    const size_t NN = (size_t)NDIM * NDIM;
    for (int b = 0; b < BATCH; b++) {
        const float* Wb = W + (size_t)b * NN;
        // load direct tile T1 = W[b, i-rows, j-cols], swapped tile T2 = W[b, j-rows, i-cols]
        {
            float4 v = *(const float4*)&Wb[(size_t)(i0 + ty) * NDIM + j0 + 4 * tx];
            T1[ty][4 * tx + 0] = v.x; T1[ty][4 * tx + 1] = v.y;
            T1[ty][4 * tx + 2] = v.z; T1[ty][4 * tx + 3] = v.w;
            float4 u = *(const float4*)&Wb[(size_t)(j0 + ty) * NDIM + i0 + 4 * tx];
            T2[ty][4 * tx + 0] = u.x; T2[ty][4 * tx + 1] = u.y;
            T2[ty][4 * tx + 2] = u.z; T2[ty][4 * tx + 3] = u.w;
        }
        __syncthreads();

        // Pass A: output rows i = i0+ty, cols j0+4tx..+3
        {
            float4 sv;
            float s0 = 0.5f * (T1[ty][4 * tx + 0] + T2[4 * tx + 0][ty]) * A_s[ty][4 * tx + 0];
            float s1 = 0.5f * (T1[ty][4 * tx + 1] + T2[4 * tx + 1][ty]) * A_s[ty][4 * tx + 1];
            float s2 = 0.5f * (T1[ty][4 * tx + 2] + T2[4 * tx + 2][ty]) * A_s[ty][4 * tx + 2];
            float s3 = 0.5f * (T1[ty][4 * tx + 3] + T2[4 * tx + 3][ty]) * A_s[ty][4 * tx + 3];
            sv.x = s0; sv.y = s1; sv.z = s2; sv.w = s3;
            *(float4*)&g_K0[(size_t)b * NN + (size_t)(i0 + ty) * NDIM + j0 + 4 * tx] = sv;
            float sum = (s0 + s1) + (s2 + s3);
#pragma unroll
            for (int off = 4; off > 0; off >>= 1)
                sum += __shfl_down_sync(0xffffffffu, sum, off, 8);
            if (tx == 0)
                g_part[((size_t)b * NT + jt) * NDIM + i0 + ty] = sum;
        }

        // Pass B (off-diagonal): output rows j = j0+ty, cols i0+4tx..+3
        if (jt != it) {
            float4 sv;
            float s0 = 0.5f * (T1[4 * tx + 0][ty] + T2[ty][4 * tx + 0]) * A_s[4 * tx + 0][ty];
            float s1 = 0.5f * (T1[4 * tx + 1][ty] + T2[ty][4 * tx + 1]) * A_s[4 * tx + 1][ty];
            float s2 = 0.5f * (T1[4 * tx + 2][ty] + T2[ty][4 * tx + 2]) * A_s[4 * tx + 2][ty];
            float s3 = 0.5f * (T1[4 * tx + 3][ty] + T2[ty][4 * tx + 3]) * A_s[4 * tx + 3][ty];
            sv.x = s0; sv.y = s1; sv.z = s2; sv.w = s3;
            *(float4*)&g_K0[(size_t)b * NN + (size_t)(j0 + ty) * NDIM + i0 + 4 * tx] = sv;
            float sum = (s0 + s1) + (s2 + s3);
#pragma unroll
            for (int off = 4; off > 0; off >>= 1)
                sum += __shfl_down_sync(0xffffffffu, sum, off, 8);
            if (tx == 0)
                g_part[((size_t)b * NT + it) * NDIM + j0 + ty] = sum;
        }
        __syncthreads();
    }
}

// ---------------- kernel 2: d = rsqrt(max(sum(part), eps)) ----------------
__global__ void k_norm() {
    const int n = blockIdx.x * 256 + threadIdx.x;
    const int b = blockIdx.y;
    float s = 0.0f;
#pragma unroll 8
    for (int g = 0; g < NT; g++)
        s += g_part[((size_t)b * NT + g) * NDIM + n];
    s = fmaxf(s, 1e-12f);
    g_d[b * NDIM + n] = rsqrtf(s);
}

// ---------------- kernel 3: out[b] = ws * d .* (K0[b] @ (d .* x[b])) ------
// grid (NDIM/128, BATCH), 256 threads.
// Block tile: 128 rows (i) x 64 cols (c), k-tile 32 (m).
// Thread micro-tile: 4 i x 8 c, accumulated in packed f32x2.
__global__ void __launch_bounds__(256) k_gemm(const float* __restrict__ x,
                                              const float* __restrict__ wscale,
                                              float* __restrict__ out) {
    __shared__ float Ks[128][33];
    __shared__ __align__(16) float xs[32][64];

    const int b = blockIdx.y;
    const int i0 = blockIdx.x * 128;
    const int tid = threadIdx.x;
    const int ttx = tid & 7;    // c octet: c = 8*ttx .. +7
    const int tty = tid >> 3;   // 0..31 : i = i0 + 4*tty .. +3

    const size_t NN = (size_t)NDIM * NDIM;
    const float* K0b = g_K0 + (size_t)b * NN;
    const float* xb = x + (size_t)b * NDIM * CDIM;
    const float* db = g_d + (size_t)b * NDIM;

    unsigned long long acc[4][4];
#pragma unroll
    for (int ii = 0; ii < 4; ii++)
#pragma unroll
        for (int cc = 0; cc < 4; cc++) acc[ii][cc] = 0ull;

    for (int m0 = 0; m0 < NDIM; m0 += 32) {
        // load K0 tile 128x32 (1024 float4 / 4 per thread)
#pragma unroll
        for (int s = 0; s < 4; s++) {
            int q = tid + 256 * s;
            int r = q >> 3;
            int c4 = q & 7;
            float4 v = *(const float4*)&K0b[(size_t)(i0 + r) * NDIM + m0 + c4 * 4];
            Ks[r][c4 * 4 + 0] = v.x; Ks[r][c4 * 4 + 1] = v.y;
            Ks[r][c4 * 4 + 2] = v.z; Ks[r][c4 * 4 + 3] = v.w;
        }
        // load x tile 32x64 scaled by d[m] (512 float4 / 2 per thread)
#pragma unroll
        for (int s = 0; s < 2; s++) {
            int q = tid + 256 * s;
            int r = q >> 4;
            int c4 = q & 15;
            float dm = db[m0 + r];
            float4 v = *(const float4*)&xb[(size_t)(m0 + r) * CDIM + c4 * 4];
            v.x *= dm; v.y *= dm; v.z *= dm; v.w *= dm;
            *(float4*)&xs[r][c4 * 4] = v;
        }
        __syncthreads();

#pragma unroll
        for (int kk = 0; kk < 32; kk++) {
            unsigned long long a2[4];
#pragma unroll
            for (int ii = 0; ii < 4; ii++) {
                float a = Ks[4 * tty + ii][kk];
                a2[ii] = pack2(a, a);
            }
            float4 b0 = *(float4*)&xs[kk][8 * ttx];
            float4 b1 = *(float4*)&xs[kk][8 * ttx + 4];
            unsigned long long bb[4];
            bb[0] = pack2(b0.x, b0.y);
            bb[1] = pack2(b0.z, b0.w);
            bb[2] = pack2(b1.x, b1.y);
            bb[3] = pack2(b1.z, b1.w);
#pragma unroll
            for (int ii = 0; ii < 4; ii++)
#pragma unroll
                for (int cc = 0; cc < 4; cc++)
                    fma2(acc[ii][cc], a2[ii], bb[cc]);
        }
        __syncthreads();
    }

    const float ws = *wscale;
    float* outb = out + (size_t)b * NDIM * CDIM;
#pragma unroll
    for (int ii = 0; ii < 4; ii++) {
        int i = i0 + 4 * tty + ii;
        float sc = ws * db[i];
        float2 p0 = unpack2(acc[ii][0]);
        float2 p1 = unpack2(acc[ii][1]);
        float2 p2 = unpack2(acc[ii][2]);
        float2 p3 = unpack2(acc[ii][3]);
        float4 o0, o1;
        o0.x = p0.x * sc; o0.y = p0.y * sc; o0.z = p1.x * sc; o0.w = p1.y * sc;
        o1.x = p2.x * sc; o1.y = p2.y * sc; o1.z = p3.x * sc; o1.w = p3.y * sc;
        *(float4*)&outb[(size_t)i * CDIM + 8 * ttx] = o0;
        *(float4*)&outb[(size_t)i * CDIM + 8 * ttx + 4] = o1;
    }
}

// ---------------- launch ----------------
extern "C" void kernel_launch(void* const* d_in, const int* in_sizes, int n_in,
                              void* d_out, int out_size) {
    const float* x = (const float*)d_in[0];       // [B,N,C]
    const float* W = (const float*)d_in[1];       // [B,N,N]
    const float* U = (const float*)d_in[2];       // [N,R]
    const float* ws = (const float*)d_in[3];      // scalar
    float* out = (float*)d_out;                   // [B,N,C]

    dim3 g1(NT, NT);
    k_sym<<<g1, 256>>>(W, U);
    k_norm<<<dim3(NDIM / 256, BATCH), 256>>>();
    k_gemm<<<dim3(NDIM / 128, BATCH), 256>>>(x, ws, out);
}

// round 17
// speedup vs baseline: 1.3712x; 1.3712x over previous
#include <cuda_runtime.h>
#include <cstdint>

#define BATCH 4
#define NDIM 4096
#define CDIM 64
#define RDIM 16
#define TS 32           // k_sym tile
#define NT (NDIM / TS)  // 128 tiles per dim
#define KSPLIT 4
#define KCHUNK (NDIM / KSPLIT)   // 1024

// ---------------- scratch (device globals; no allocations) ----------------
__device__ float g_K0[(size_t)BATCH * NDIM * NDIM];   // 268 MB: Ws * A
__device__ float g_part[BATCH * NT * NDIM];           // 8 MB: deg partials
__device__ float g_d[BATCH * NDIM];                   // rsqrt(deg)
__device__ float g_outp[(size_t)KSPLIT * BATCH * NDIM * CDIM];  // 16 MB split-K partials

// ---------------- helpers ----------------
__device__ __forceinline__ float fast_sigmoid(float z) {
    float az = fabsf(z);
    if (az < 0.25f) {
        // sigmoid Taylor: 1/2 + z/4 - z^3/48 + z^5/480 ; err <= |z|^7*17/80640
        float z2 = z * z;
        return 0.5f + z * (0.25f + z2 * (-1.0f / 48.0f + z2 * (1.0f / 480.0f)));
    }
    return 1.0f / (1.0f + __expf(-z));
}

__device__ __forceinline__ unsigned long long pack2(float lo, float hi) {
    unsigned long long r;
    asm("mov.b64 %0, {%1, %2};" : "=l"(r) : "f"(lo), "f"(hi));
    return r;
}
__device__ __forceinline__ float2 unpack2(unsigned long long v) {
    float2 f;
    asm("mov.b64 {%0, %1}, %2;" : "=f"(f.x), "=f"(f.y) : "l"(v));
    return f;
}
__device__ __forceinline__ void fma2(unsigned long long& d,
                                     unsigned long long a,
                                     unsigned long long b) {
    asm("fma.rn.f32x2 %0, %1, %2, %3;" : "=l"(d) : "l"(a), "l"(b), "l"(d));
}

// ---------------- kernel 1: symmetric K0 = Ws .* A, deg partials ----------
// grid (NT, NT): blockIdx.x = jt, blockIdx.y = it, process only jt >= it.
// 256 threads: ty = tid>>3 (row 0..31), tx = tid&7 (4-col group).
__global__ void __launch_bounds__(256) k_sym(const float* __restrict__ W,
                                             const float* __restrict__ U) {
    const int jt = blockIdx.x;
    const int it = blockIdx.y;
    if (jt < it) return;

    __shared__ float A_s[TS][TS + 1];
    __shared__ float T1[TS][TS + 1];
    __shared__ float T2[TS][TS + 1];
    __shared__ float Ui[TS][RDIM + 1];
    __shared__ float Uj[TS][RDIM + 1];

    const int tid = threadIdx.x;
    const int tx = tid & 7;
    const int ty = tid >> 3;
    const int i0 = it * TS;
    const int j0 = jt * TS;

    // load U tiles (32 rows x 16) : threads 0..127 -> Ui, 128..255 -> Uj
    {
        int t = tid & 127;
        int r = t >> 2;
        int q = t & 3;
        if (tid < 128) {
            float4 v = *(const float4*)&U[(size_t)(i0 + r) * RDIM + q * 4];
            Ui[r][q * 4 + 0] = v.x; Ui[r][q * 4 + 1] = v.y;
            Ui[r][q * 4 + 2] = v.z; Ui[r][q * 4 + 3] = v.w;
        } else {
            float4 v = *(const float4*)&U[(size_t)(j0 + r) * RDIM + q * 4];
            Uj[r][q * 4 + 0] = v.x; Uj[r][q * 4 + 1] = v.y;
            Uj[r][q * 4 + 2] = v.z; Uj[r][q * 4 + 3] = v.w;
        }
    }
    __syncthreads();

    // A tile: thread handles row ty, cols 4*tx .. 4*tx+3
    {
        float ui[RDIM];
#pragma unroll
        for (int k = 0; k < RDIM; k++) ui[k] = Ui[ty][k];
#pragma unroll
        for (int jj = 0; jj < 4; jj++) {
            int j = 4 * tx + jj;
            float z = 0.0f;
#pragma unroll
            for (int k = 0; k < RDIM; k++) z = fmaf(ui[k], Uj[j][k], z);
            A_s[ty][j] = fast_sigmoid(z);
        }
    }
    __syncthreads();

    const size_t NN = (size_t)NDIM * NDIM;
    for (int b = 0; b < BATCH; b++) {
        const float* Wb = W + (size_t)b * NN;
        // load direct tile T1 = W[b, i-rows, j-cols], swapped tile T2 = W[b, j-rows, i-cols]
        {
            float4 v = *(const float4*)&Wb[(size_t)(i0 + ty) * NDIM + j0 + 4 * tx];
            T1[ty][4 * tx + 0] = v.x; T1[ty][4 * tx + 1] = v.y;
            T1[ty][4 * tx + 2] = v.z; T1[ty][4 * tx + 3] = v.w;
            float4 u = *(const float4*)&Wb[(size_t)(j0 + ty) * NDIM + i0 + 4 * tx];
            T2[ty][4 * tx + 0] = u.x; T2[ty][4 * tx + 1] = u.y;
            T2[ty][4 * tx + 2] = u.z; T2[ty][4 * tx + 3] = u.w;
        }
        __syncthreads();

        // Pass A: output rows i = i0+ty, cols j0+4tx..+3
        {
            float4 sv;
            float s0 = 0.5f * (T1[ty][4 * tx + 0] + T2[4 * tx + 0][ty]) * A_s[ty][4 * tx + 0];
            float s1 = 0.5f * (T1[ty][4 * tx + 1] + T2[4 * tx + 1][ty]) * A_s[ty][4 * tx + 1];
            float s2 = 0.5f * (T1[ty][4 * tx + 2] + T2[4 * tx + 2][ty]) * A_s[ty][4 * tx + 2];
            float s3 = 0.5f * (T1[ty][4 * tx + 3] + T2[4 * tx + 3][ty]) * A_s[ty][4 * tx + 3];
            sv.x = s0; sv.y = s1; sv.z = s2; sv.w = s3;
            *(float4*)&g_K0[(size_t)b * NN + (size_t)(i0 + ty) * NDIM + j0 + 4 * tx] = sv;
            float sum = (s0 + s1) + (s2 + s3);
#pragma unroll
            for (int off = 4; off > 0; off >>= 1)
                sum += __shfl_down_sync(0xffffffffu, sum, off, 8);
            if (tx == 0)
                g_part[((size_t)b * NT + jt) * NDIM + i0 + ty] = sum;
        }

        // Pass B (off-diagonal): output rows j = j0+ty, cols i0+4tx..+3
        if (jt != it) {
            float4 sv;
            float s0 = 0.5f * (T1[4 * tx + 0][ty] + T2[ty][4 * tx + 0]) * A_s[4 * tx + 0][ty];
            float s1 = 0.5f * (T1[4 * tx + 1][ty] + T2[ty][4 * tx + 1]) * A_s[4 * tx + 1][ty];
            float s2 = 0.5f * (T1[4 * tx + 2][ty] + T2[ty][4 * tx + 2]) * A_s[4 * tx + 2][ty];
            float s3 = 0.5f * (T1[4 * tx + 3][ty] + T2[ty][4 * tx + 3]) * A_s[4 * tx + 3][ty];
            sv.x = s0; sv.y = s1; sv.z = s2; sv.w = s3;
            *(float4*)&g_K0[(size_t)b * NN + (size_t)(j0 + ty) * NDIM + i0 + 4 * tx] = sv;
            float sum = (s0 + s1) + (s2 + s3);
#pragma unroll
            for (int off = 4; off > 0; off >>= 1)
                sum += __shfl_down_sync(0xffffffffu, sum, off, 8);
            if (tx == 0)
                g_part[((size_t)b * NT + it) * NDIM + j0 + ty] = sum;
        }
        __syncthreads();
    }
}

// ---------------- kernel 2: d = rsqrt(max(sum(part), eps)) ----------------
__global__ void k_norm() {
    const int n = blockIdx.x * 256 + threadIdx.x;
    const int b = blockIdx.y;
    float s = 0.0f;
#pragma unroll 8
    for (int g = 0; g < NT; g++)
        s += g_part[((size_t)b * NT + g) * NDIM + n];
    s = fmaxf(s, 1e-12f);
    g_d[b * NDIM + n] = rsqrtf(s);
}

// ---------------- kernel 3: split-K GEMM partials ------------------------
// outp[ks,b,i,c] = sum_{m in ks-chunk} K0[b,i,m] * (d[b,m]*x[b,m,c])
// grid (NDIM/64, BATCH, KSPLIT), 128 threads.
// Block tile: 64 rows (i) x 64 cols (c), k-tile 32 (m).
// Thread micro-tile: 4 i x 8 c, accumulated in packed f32x2.
__global__ void __launch_bounds__(128) k_gemm(const float* __restrict__ x) {
    __shared__ float Ks[64][33];
    __shared__ __align__(16) float xs[32][64];

    const int b = blockIdx.y;
    const int ksp = blockIdx.z;
    const int i0 = blockIdx.x * 64;
    const int tid = threadIdx.x;
    const int ttx = tid & 7;    // c octet: c = 8*ttx .. +7
    const int tty = tid >> 3;   // 0..15 : i = i0 + 4*tty .. +3

    const size_t NN = (size_t)NDIM * NDIM;
    const float* K0b = g_K0 + (size_t)b * NN;
    const float* xb = x + (size_t)b * NDIM * CDIM;
    const float* db = g_d + (size_t)b * NDIM;

    unsigned long long acc[4][4];
#pragma unroll
    for (int ii = 0; ii < 4; ii++)
#pragma unroll
        for (int cc = 0; cc < 4; cc++) acc[ii][cc] = 0ull;

    const int mbeg = ksp * KCHUNK;
    const int mend = mbeg + KCHUNK;
    for (int m0 = mbeg; m0 < mend; m0 += 32) {
        // load K0 tile 64x32 (512 float4 / 4 per thread)
#pragma unroll
        for (int s = 0; s < 4; s++) {
            int q = tid + 128 * s;
            int r = q >> 3;
            int c4 = q & 7;
            float4 v = *(const float4*)&K0b[(size_t)(i0 + r) * NDIM + m0 + c4 * 4];
            Ks[r][c4 * 4 + 0] = v.x; Ks[r][c4 * 4 + 1] = v.y;
            Ks[r][c4 * 4 + 2] = v.z; Ks[r][c4 * 4 + 3] = v.w;
        }
        // load x tile 32x64 scaled by d[m] (512 float4 / 4 per thread)
#pragma unroll
        for (int s = 0; s < 4; s++) {
            int q = tid + 128 * s;
            int r = q >> 4;
            int c4 = q & 15;
            float dm = db[m0 + r];
            float4 v = *(const float4*)&xb[(size_t)(m0 + r) * CDIM + c4 * 4];
            v.x *= dm; v.y *= dm; v.z *= dm; v.w *= dm;
            *(float4*)&xs[r][c4 * 4] = v;
        }
        __syncthreads();

#pragma unroll
        for (int kk = 0; kk < 32; kk++) {
            unsigned long long a2[4];
#pragma unroll
            for (int ii = 0; ii < 4; ii++) {
                float a = Ks[4 * tty + ii][kk];
                a2[ii] = pack2(a, a);
            }
            float4 b0 = *(float4*)&xs[kk][8 * ttx];
            float4 b1 = *(float4*)&xs[kk][8 * ttx + 4];
            unsigned long long bb[4];
            bb[0] = pack2(b0.x, b0.y);
            bb[1] = pack2(b0.z, b0.w);
            bb[2] = pack2(b1.x, b1.y);
            bb[3] = pack2(b1.z, b1.w);
#pragma unroll
            for (int ii = 0; ii < 4; ii++)
#pragma unroll
                for (int cc = 0; cc < 4; cc++)
                    fma2(acc[ii][cc], a2[ii], bb[cc]);
        }
        __syncthreads();
    }

    float* pb = g_outp + ((size_t)ksp * BATCH + b) * NDIM * CDIM;
#pragma unroll
    for (int ii = 0; ii < 4; ii++) {
        int i = i0 + 4 * tty + ii;
        float2 p0 = unpack2(acc[ii][0]);
        float2 p1 = unpack2(acc[ii][1]);
        float2 p2 = unpack2(acc[ii][2]);
        float2 p3 = unpack2(acc[ii][3]);
        float4 o0, o1;
        o0.x = p0.x; o0.y = p0.y; o0.z = p1.x; o0.w = p1.y;
        o1.x = p2.x; o1.y = p2.y; o1.z = p3.x; o1.w = p3.y;
        *(float4*)&pb[(size_t)i * CDIM + 8 * ttx] = o0;
        *(float4*)&pb[(size_t)i * CDIM + 8 * ttx + 4] = o1;
    }
}

// ---------------- kernel 4: reduce split-K + scale by ws * d_i ------------
// One thread per output float4: out[b,i,c4] = ws*d[b,i]*sum_ks outp[ks,b,i,c4]
__global__ void __launch_bounds__(256) k_red(const float* __restrict__ wscale,
                                             float* __restrict__ out) {
    const int idx = blockIdx.x * 256 + threadIdx.x;     // 0 .. B*N*C/4-1
    const int c = (idx & 15) * 4;
    const int i = (idx >> 4) & (NDIM - 1);
    const int b = idx >> 16;
    const size_t off = ((size_t)b * NDIM + i) * CDIM + c;
    const size_t stride = (size_t)BATCH * NDIM * CDIM;

    float4 s = make_float4(0.f, 0.f, 0.f, 0.f);
#pragma unroll
    for (int ks = 0; ks < KSPLIT; ks++) {
        float4 v = *(const float4*)&g_outp[(size_t)ks * stride + off];
        s.x += v.x; s.y += v.y; s.z += v.z; s.w += v.w;
    }
    const float sc = wscale[0] * g_d[b * NDIM + i];
    s.x *= sc; s.y *= sc; s.z *= sc; s.w *= sc;
    *(float4*)&out[off] = s;
}

// ---------------- launch ----------------
extern "C" void kernel_launch(void* const* d_in, const int* in_sizes, int n_in,
                              void* d_out, int out_size) {
    const float* x = (const float*)d_in[0];       // [B,N,C]
    const float* W = (const float*)d_in[1];       // [B,N,N]
    const float* U = (const float*)d_in[2];       // [N,R]
    const float* ws = (const float*)d_in[3];      // scalar
    float* out = (float*)d_out;                   // [B,N,C]

    dim3 g1(NT, NT);
    k_sym<<<g1, 256>>>(W, U);
    k_norm<<<dim3(NDIM / 256, BATCH), 256>>>();
    k_gemm<<<dim3(NDIM / 64, BATCH, KSPLIT), 128>>>(x);
    k_red<<<(BATCH * NDIM * CDIM / 4) / 256, 256>>>(ws, out);
}